// round 1
// baseline (speedup 1.0000x reference)
#include <cuda_runtime.h>
#include <math.h>

#define NN 10000
#define EE 160000
#define SD 256
#define DINK 600
#define TAILD 88

#define OFFV 2560000   // N*256
#define OFFP 6400000   // +N*384
#define OFFE 6430000   // +N*3

typedef unsigned long long ull;

// ---------------- device scratch (no allocations allowed) ----------------
__device__ __align__(16) float g_s[NN * SD];
__device__ __align__(16) float g_v[NN * 384];
__device__ __align__(16) float g_sacc[NN * SD];
__device__ __align__(16) float g_vacc[NN * 384];
__device__ __align__(16) float g_h[(size_t)EE * SD];
__device__ __align__(16) float g_tail[(size_t)EE * TAILD];
__device__ __align__(16) float g_vv[NN * 384];
__device__ __align__(16) float g_nv[NN * 128];
__device__ __align__(16) float g_h2[NN * SD];
__device__ float g_cnt[NN];
__device__ float g_icnt[NN];

// ---------------- packed f32x2 helpers (Blackwell FFMA2 path) ----------------
__device__ __forceinline__ ull pk2(float lo, float hi) {
    ull r; asm("mov.b64 %0, {%1,%2};" : "=l"(r) : "f"(lo), "f"(hi)); return r;
}
__device__ __forceinline__ ull fma2(ull a, ull b, ull c) {
    ull d; asm("fma.rn.f32x2 %0, %1, %2, %3;" : "=l"(d) : "l"(a), "l"(b), "l"(c)); return d;
}
__device__ __forceinline__ float2 upk(ull x) {
    float2 f; asm("mov.b64 {%0,%1}, %2;" : "=f"(f.x), "=f"(f.y) : "l"(x)); return f;
}
__device__ __forceinline__ float siluf(float x) { return x / (1.f + __expf(-x)); }

__device__ __forceinline__ float blockReduceSum(float v, float* red) {
    int t = threadIdx.x;
    red[t] = v; __syncthreads();
    for (int s = blockDim.x >> 1; s > 0; s >>= 1) {
        if (t < s) red[t] += red[t + s];
        __syncthreads();
    }
    float r = red[0]; __syncthreads();
    return r;
}

// ---------------- init: copy state, passthrough outputs, zero counts ----------------
__global__ void k_init(const float* __restrict__ s_in, const float* __restrict__ v_in,
                       const float* __restrict__ p_in, const float* __restrict__ ee_in,
                       float* __restrict__ out) {
    int gs = gridDim.x * blockDim.x;
    int i0 = blockIdx.x * blockDim.x + threadIdx.x;
    for (int i = i0; i < NN * SD; i += gs)  g_s[i] = s_in[i];
    for (int i = i0; i < NN * 384; i += gs) g_v[i] = v_in[i];
    for (int i = i0; i < NN * 3; i += gs)   out[OFFP + i] = p_in[i];
    for (int i = i0; i < EE * 32; i += gs)  out[OFFE + i] = ee_in[i];
    for (int i = i0; i < NN; i += gs)       g_cnt[i] = 0.f;
}

__global__ void k_count(const int* __restrict__ tgt) {
    int i = blockIdx.x * blockDim.x + threadIdx.x;
    if (i < EE) atomicAdd(&g_cnt[tgt[i]], 1.0f);
}
__global__ void k_icnt() {
    int i = blockIdx.x * blockDim.x + threadIdx.x;
    if (i < NN) g_icnt[i] = 1.0f / fmaxf(g_cnt[i], 1.0f);
}

// ---------------- edge static tail features: rbf(20) | a(1) | e(32) | ohe(3) | glob(32) ----------------
__global__ void k_tail(const float* __restrict__ ed, const float* __restrict__ ea,
                       const float* __restrict__ ee, const float* __restrict__ ohe,
                       const float* __restrict__ eg) {
    int idx = blockIdx.x * blockDim.x + threadIdx.x;
    if (idx >= EE * TAILD) return;
    int e = idx / TAILD;
    int j = idx - e * TAILD;
    float val;
    if (j < 20) {
        float d = ed[e];
        float mu = (5.0f / 19.0f) * (float)j;
        float diff = d - mu;
        float env = (d < 5.0f) ? 0.5f * (cosf(3.14159265358979f * d * 0.2f) + 1.0f) : 0.0f;
        val = expf(-8.0f * diff * diff) * env;   // coeff = -0.5/(5/20)^2 = -8
    } else if (j == 20) val = ea[e];
    else if (j < 53)    val = ee[e * 32 + (j - 21)];
    else if (j < 56)    val = ohe[e * 3 + (j - 53)];
    else                val = eg[e * 32 + (j - 56)];
    g_tail[idx] = val;
}

// ---------------- per-node: LayerNorm(s), vnorm(v), zero accumulators ----------------
__global__ void k_prep(const float* __restrict__ gamma, const float* __restrict__ beta) {
    __shared__ float red[256];
    int n = blockIdx.x, t = threadIdx.x;
    size_t sb = (size_t)n * SD;
    float x = g_s[sb + t];
    float mu = blockReduceSum(x, red) * (1.f / 256.f);
    float d = x - mu;
    float var = blockReduceSum(d * d, red) * (1.f / 256.f);
    float rstd = rsqrtf(var + 1e-6f);
    g_s[sb + t] = d * rstd * gamma[t] + beta[t];

    size_t vb = (size_t)n * 384;
    float v0 = g_v[vb + t];
    float v1 = (t < 128) ? g_v[vb + 256 + t] : 0.f;
    float msq = blockReduceSum(v0 * v0 + v1 * v1, red) * (1.f / 128.f);
    float rs = rsqrtf(msq + 1e-6f);
    g_v[vb + t] = v0 * rs;
    if (t < 128) g_v[vb + 256 + t] = v1 * rs;

    g_sacc[sb + t] = 0.f;
    g_vacc[vb + t] = 0.f;
    if (t < 128) g_vacc[vb + 256 + t] = 0.f;
}

__global__ void k_final(const float* __restrict__ gamma, const float* __restrict__ beta,
                        float* __restrict__ outs, float* __restrict__ outv) {
    __shared__ float red[256];
    int n = blockIdx.x, t = threadIdx.x;
    size_t sb = (size_t)n * SD;
    float x = g_s[sb + t];
    float mu = blockReduceSum(x, red) * (1.f / 256.f);
    float d = x - mu;
    float var = blockReduceSum(d * d, red) * (1.f / 256.f);
    float rstd = rsqrtf(var + 1e-6f);
    outs[sb + t] = d * rstd * gamma[t] + beta[t];

    size_t vb = (size_t)n * 384;
    float v0 = g_v[vb + t];
    float v1 = (t < 128) ? g_v[vb + 256 + t] : 0.f;
    float msq = blockReduceSum(v0 * v0 + v1 * v1, red) * (1.f / 128.f);
    float rs = rsqrtf(msq + 1e-6f);
    outv[vb + t] = v0 * rs;
    if (t < 128) outv[vb + 256 + t] = v1 * rs;
}

// ---------------- edge GEMM1: h = silu(feat @ We1 + be1), feat gathered on the fly ----------------
__global__ __launch_bounds__(256) void k_gemm1(const int* __restrict__ src, const int* __restrict__ tgt,
                                               const float* __restrict__ W, const float* __restrict__ bias) {
    __shared__ float As[8][68];
    __shared__ float Bs[8][256];
    __shared__ int s_src[64], s_tgt[64];
    const int e0 = blockIdx.x * 64;
    const int tid = threadIdx.x;
    if (tid < 64) { s_src[tid] = src[e0 + tid]; s_tgt[tid] = tgt[e0 + tid]; }
    __syncthreads();
    const int tr = tid >> 4, tc = tid & 15;
    const int le = tid >> 2, lc = tid & 3;

    ull acc[4][8];
#pragma unroll
    for (int r = 0; r < 4; r++)
#pragma unroll
        for (int j = 0; j < 8; j++) acc[r][j] = 0ull;

    for (int k0 = 0; k0 < DINK; k0 += 8) {
        // A tile: feat[e0..e0+63][k0..k0+7], segment-uniform per tile (256|512 boundaries)
        {
            int k = k0 + lc * 2;
            float2 f;
            if (k < 512) {
                int row = (k < 256) ? s_src[le] : s_tgt[le];
                f = *reinterpret_cast<const float2*>(&g_s[(size_t)row * SD + (k & 255)]);
            } else {
                f = *reinterpret_cast<const float2*>(&g_tail[(size_t)(e0 + le) * TAILD + (k - 512)]);
            }
            As[lc * 2][le] = f.x;
            As[lc * 2 + 1][le] = f.y;
        }
        // B tile: We1[k0..k0+7][0..255]
#pragma unroll
        for (int i = tid; i < 512; i += 256) {
            int kk = i >> 6, n4 = i & 63;
            *reinterpret_cast<float4*>(&Bs[kk][n4 * 4]) =
                *reinterpret_cast<const float4*>(&W[(size_t)(k0 + kk) * SD + n4 * 4]);
        }
        __syncthreads();
#pragma unroll
        for (int kk = 0; kk < 8; kk++) {
            float4 av = *reinterpret_cast<const float4*>(&As[kk][tr * 4]);
            const ull* bp = reinterpret_cast<const ull*>(&Bs[kk][tc * 16]);
            ull b[8];
#pragma unroll
            for (int j = 0; j < 8; j++) b[j] = bp[j];
            ull aa[4] = {pk2(av.x, av.x), pk2(av.y, av.y), pk2(av.z, av.z), pk2(av.w, av.w)};
#pragma unroll
            for (int r = 0; r < 4; r++)
#pragma unroll
                for (int j = 0; j < 8; j++) acc[r][j] = fma2(aa[r], b[j], acc[r][j]);
        }
        __syncthreads();
    }
#pragma unroll
    for (int r = 0; r < 4; r++) {
        float* hrow = &g_h[(size_t)(e0 + tr * 4 + r) * SD];
#pragma unroll
        for (int j = 0; j < 8; j++) {
            float2 c = upk(acc[r][j]);
            int n = tc * 16 + j * 2;
            float x0 = c.x + bias[n], x1 = c.y + bias[n + 1];
            float2 o = make_float2(siluf(x0), siluf(x1));
            *reinterpret_cast<float2*>(&hrow[n]) = o;
        }
    }
}

// ---------------- edge GEMM2 + message scatter (blockIdx.y: 0 -> ms half, 1 -> gr/gv half) ----------------
__global__ __launch_bounds__(256) void k_gemm2(const float* __restrict__ W, const float* __restrict__ bias,
                                               const int* __restrict__ src, const int* __restrict__ tgt,
                                               const float* __restrict__ rnorm) {
    __shared__ float As[8][68];
    __shared__ float Bs[8][256];
    __shared__ int s_src[64], s_tgt[64];
    const int e0 = blockIdx.x * 64;
    const int by = blockIdx.y;
    const int tid = threadIdx.x;
    if (tid < 64) { s_src[tid] = src[e0 + tid]; s_tgt[tid] = tgt[e0 + tid]; }
    __syncthreads();
    const int tr = tid >> 4, tc = tid & 15;
    const int le = tid >> 2, lc = tid & 3;
    const float* wbase = W + by * 256;
    const float* bl = bias + by * 256;

    ull acc[4][8];
#pragma unroll
    for (int r = 0; r < 4; r++)
#pragma unroll
        for (int j = 0; j < 8; j++) acc[r][j] = 0ull;

    for (int k0 = 0; k0 < SD; k0 += 8) {
        {
            int k = k0 + lc * 2;
            float2 f = *reinterpret_cast<const float2*>(&g_h[(size_t)(e0 + le) * SD + k]);
            As[lc * 2][le] = f.x;
            As[lc * 2 + 1][le] = f.y;
        }
#pragma unroll
        for (int i = tid; i < 512; i += 256) {
            int kk = i >> 6, n4 = i & 63;
            *reinterpret_cast<float4*>(&Bs[kk][n4 * 4]) =
                *reinterpret_cast<const float4*>(&wbase[(size_t)(k0 + kk) * 512 + n4 * 4]);
        }
        __syncthreads();
#pragma unroll
        for (int kk = 0; kk < 8; kk++) {
            float4 av = *reinterpret_cast<const float4*>(&As[kk][tr * 4]);
            const ull* bp = reinterpret_cast<const ull*>(&Bs[kk][tc * 16]);
            ull b[8];
#pragma unroll
            for (int j = 0; j < 8; j++) b[j] = bp[j];
            ull aa[4] = {pk2(av.x, av.x), pk2(av.y, av.y), pk2(av.z, av.z), pk2(av.w, av.w)};
#pragma unroll
            for (int r = 0; r < 4; r++)
#pragma unroll
                for (int j = 0; j < 8; j++) acc[r][j] = fma2(aa[r], b[j], acc[r][j]);
        }
        __syncthreads();
    }

    if (by == 0) {
        // ms -> segment-sum into g_sacc[tgt]
#pragma unroll
        for (int r = 0; r < 4; r++) {
            float* srow = &g_sacc[(size_t)s_tgt[tr * 4 + r] * SD];
#pragma unroll
            for (int j = 0; j < 8; j++) {
                float2 c = upk(acc[r][j]);
                int n = tc * 16 + j * 2;
                atomicAdd(&srow[n], c.x + bl[n]);
                atomicAdd(&srow[n + 1], c.y + bl[n + 1]);
            }
        }
    } else {
        // gr (cols 0..127) and gv (cols 128..255): mv = gr*rnorm + gv*v[src] -> g_vacc[tgt]
#pragma unroll
        for (int r = 0; r < 4; r++) {
            int l2 = tr * 4 + r;
            int eg = e0 + l2;
            float* vrow = &g_vacc[(size_t)s_tgt[l2] * 384];
            float rn0 = rnorm[eg * 3 + 0];
            float rn1 = rnorm[eg * 3 + 1];
            float rn2 = rnorm[eg * 3 + 2];
            if (tc < 8) {
#pragma unroll
                for (int j = 0; j < 8; j++) {
                    float2 c = upk(acc[r][j]);
                    int n = tc * 16 + j * 2;
                    float gx = c.x + bl[n], gy = c.y + bl[n + 1];
                    int d = n;
                    atomicAdd(&vrow[d], gx * rn0);
                    atomicAdd(&vrow[128 + d], gx * rn1);
                    atomicAdd(&vrow[256 + d], gx * rn2);
                    atomicAdd(&vrow[d + 1], gy * rn0);
                    atomicAdd(&vrow[128 + d + 1], gy * rn1);
                    atomicAdd(&vrow[256 + d + 1], gy * rn2);
                }
            } else {
                const float* vsrc = &g_v[(size_t)s_src[l2] * 384];
#pragma unroll
                for (int j = 0; j < 8; j++) {
                    float2 c = upk(acc[r][j]);
                    int n = tc * 16 + j * 2;
                    float gx = c.x + bl[n], gy = c.y + bl[n + 1];
                    int d = n - 128;
#pragma unroll
                    for (int cc = 0; cc < 3; cc++) {
                        float2 vv2 = *reinterpret_cast<const float2*>(&vsrc[cc * 128 + d]);
                        atomicAdd(&vrow[cc * 128 + d], gx * vv2.x);
                        atomicAdd(&vrow[cc * 128 + d + 1], gy * vv2.y);
                    }
                }
            }
        }
    }
}

// ---------------- node: add averaged messages ----------------
__global__ void k_add() {
    int n = blockIdx.x, t = threadIdx.x;  // 384 threads
    float ic = g_icnt[n];
    if (t < 256) g_s[(size_t)n * SD + t] += g_sacc[(size_t)n * SD + t] * ic;
    g_v[(size_t)n * 384 + t] += g_vacc[(size_t)n * 384 + t] * ic;
}

// ---------------- node update: vv = v @ Wvu, nv = |vv| ----------------
__global__ void k_vv(const float* __restrict__ W) {
    __shared__ float vs[384];
    int n = blockIdx.x, t = threadIdx.x;  // 128 threads
    size_t vb = (size_t)n * 384;
    vs[t] = g_v[vb + t];
    vs[128 + t] = g_v[vb + 128 + t];
    vs[256 + t] = g_v[vb + 256 + t];
    __syncthreads();
    float a0 = 0.f, a1 = 0.f, a2 = 0.f;
#pragma unroll 8
    for (int k = 0; k < 128; k++) {
        float w = W[(size_t)k * 128 + t];
        a0 += vs[k] * w;
        a1 += vs[128 + k] * w;
        a2 += vs[256 + k] * w;
    }
    g_vv[vb + t] = a0;
    g_vv[vb + 128 + t] = a1;
    g_vv[vb + 256 + t] = a2;
    g_nv[(size_t)n * 128 + t] = sqrtf(a0 * a0 + a1 * a1 + a2 * a2 + 1e-6f);
}

// ---------------- node update MLP: h2 = silu([s, nv] @ Wu1 + bu1) ----------------
__global__ void k_u1(const float* __restrict__ W, const float* __restrict__ b) {
    __shared__ float xs[384];
    int n = blockIdx.x, t = threadIdx.x;  // 256 threads
    xs[t] = g_s[(size_t)n * SD + t];
    if (t < 128) xs[256 + t] = g_nv[(size_t)n * 128 + t];
    __syncthreads();
    float acc = b[t];
#pragma unroll 8
    for (int k = 0; k < 384; k++) acc += xs[k] * W[(size_t)k * 256 + t];
    g_h2[(size_t)n * SD + t] = siluf(acc);
}

// ---------------- node update MLP out: u = h2 @ Wu2 + bu2; s += u[:256]; v += vv*u[256:] ----------------
__global__ void k_u2(const float* __restrict__ W, const float* __restrict__ b) {
    __shared__ float hs[256];
    int n = blockIdx.x, t = threadIdx.x;  // 384 threads
    if (t < 256) hs[t] = g_h2[(size_t)n * SD + t];
    __syncthreads();
    float acc = b[t];
#pragma unroll 8
    for (int k = 0; k < 256; k++) acc += hs[k] * W[(size_t)k * 384 + t];
    if (t < 256) {
        g_s[(size_t)n * SD + t] += acc;
    } else {
        int d = t - 256;
        size_t vb = (size_t)n * 384;
        g_v[vb + d]       += g_vv[vb + d] * acc;
        g_v[vb + 128 + d] += g_vv[vb + 128 + d] * acc;
        g_v[vb + 256 + d] += g_vv[vb + 256 + d] * acc;
    }
}

// ---------------- launch ----------------
extern "C" void kernel_launch(void* const* d_in, const int* in_sizes, int n_in,
                              void* d_out, int out_size) {
    const float* s_in   = (const float*)d_in[0];
    const float* v_in   = (const float*)d_in[1];
    const float* p_in   = (const float*)d_in[2];
    const int*   eidx   = (const int*)d_in[3];
    const float* edge_d = (const float*)d_in[4];
    const float* edge_a = (const float*)d_in[5];
    const float* rnorm  = (const float*)d_in[6];
    const float* edge_e = (const float*)d_in[7];
    const float* ohe    = (const float*)d_in[8];
    const float* eglob  = (const float*)d_in[9];
    const float* gamma  = (const float*)d_in[10];
    const float* beta   = (const float*)d_in[11];
    const float* We1    = (const float*)d_in[12];
    const float* be1    = (const float*)d_in[13];
    const float* We2    = (const float*)d_in[14];
    const float* be2    = (const float*)d_in[15];
    const float* Wvu    = (const float*)d_in[16];
    const float* Wu1    = (const float*)d_in[17];
    const float* bu1    = (const float*)d_in[18];
    const float* Wu2    = (const float*)d_in[19];
    const float* bu2    = (const float*)d_in[20];

    const int* src = eidx;
    const int* tgt = eidx + EE;
    float* out = (float*)d_out;

    k_init<<<2048, 256>>>(s_in, v_in, p_in, edge_e, out);
    k_count<<<(EE + 255) / 256, 256>>>(tgt);
    k_icnt<<<(NN + 255) / 256, 256>>>();
    k_tail<<<(EE * TAILD + 255) / 256, 256>>>(edge_d, edge_a, edge_e, ohe, eglob);

    for (int i = 0; i < 5; i++) {
        k_prep<<<NN, 256>>>(gamma + i * 256, beta + i * 256);
        k_gemm1<<<EE / 64, 256>>>(src, tgt, We1 + (size_t)i * DINK * SD, be1 + i * 256);
        k_gemm2<<<dim3(EE / 64, 2), 256>>>(We2 + (size_t)i * SD * 512, be2 + i * 512, src, tgt, rnorm);
        k_add<<<NN, 384>>>();
        if (i < 4) {
            k_vv<<<NN, 128>>>(Wvu + (size_t)i * 128 * 128);
            k_u1<<<NN, 256>>>(Wu1 + (size_t)i * 384 * 256, bu1 + i * 256);
            k_u2<<<NN, 384>>>(Wu2 + (size_t)i * 256 * 384, bu2 + i * 384);
        }
    }
    k_final<<<NN, 256>>>(gamma + 5 * 256, beta + 5 * 256, out, out + OFFV);
}

// round 2
// speedup vs baseline: 3.4259x; 3.4259x over previous
#include <cuda_runtime.h>
#include <math.h>

#define NN 10000
#define EE 160000
#define SD 256
#define TAILD 88

#define OFFV 2560000   // N*256
#define OFFP 6400000   // +N*384
#define OFFE 6430000   // +N*3

typedef unsigned long long ull;

// ---------------- device scratch (no allocations allowed) ----------------
__device__ __align__(16) float g_s[NN * SD];
__device__ __align__(16) float g_v[NN * 384];
__device__ __align__(16) float g_sacc[NN * SD];
__device__ __align__(16) float g_vacc[NN * 384];
__device__ __align__(16) float g_h[(size_t)EE * SD];
__device__ __align__(16) float g_tail[(size_t)EE * TAILD];
__device__ __align__(16) float g_vv[NN * 384];
__device__ __align__(16) float g_nv[NN * 128];
__device__ __align__(16) float g_h2[NN * SD];
__device__ float g_cnt[NN];
__device__ float g_icnt[NN];

// ---------------- helpers ----------------
__device__ __forceinline__ ull pk2(float lo, float hi) {
    ull r; asm("mov.b64 %0, {%1,%2};" : "=l"(r) : "f"(lo), "f"(hi)); return r;
}
__device__ __forceinline__ ull fma2(ull a, ull b, ull c) {
    ull d; asm("fma.rn.f32x2 %0, %1, %2, %3;" : "=l"(d) : "l"(a), "l"(b), "l"(c)); return d;
}
__device__ __forceinline__ float2 upk(ull x) {
    float2 f; asm("mov.b64 {%0,%1}, %2;" : "=f"(f.x), "=f"(f.y) : "l"(x)); return f;
}
__device__ __forceinline__ float siluf(float x) { return x / (1.f + __expf(-x)); }

__device__ __forceinline__ void cpasync16(void* sdst, const void* gsrc) {
    unsigned sa = (unsigned)__cvta_generic_to_shared(sdst);
    asm volatile("cp.async.cg.shared.global [%0], [%1], 16;" :: "r"(sa), "l"(gsrc));
}
#define CP_COMMIT asm volatile("cp.async.commit_group;")
#define CP_WAIT1  asm volatile("cp.async.wait_group 1;" ::: "memory")
#define CP_WAIT0  asm volatile("cp.async.wait_group 0;" ::: "memory")

__device__ __forceinline__ float blockReduceSum(float v, float* red) {
    int t = threadIdx.x;
    red[t] = v; __syncthreads();
    for (int s = blockDim.x >> 1; s > 0; s >>= 1) {
        if (t < s) red[t] += red[t + s];
        __syncthreads();
    }
    float r = red[0]; __syncthreads();
    return r;
}

// ---------------- init / counts / tail ----------------
__global__ void k_init(const float* __restrict__ s_in, const float* __restrict__ v_in,
                       const float* __restrict__ p_in, const float* __restrict__ ee_in,
                       float* __restrict__ out) {
    int gs = gridDim.x * blockDim.x;
    int i0 = blockIdx.x * blockDim.x + threadIdx.x;
    for (int i = i0; i < NN * SD; i += gs)  g_s[i] = s_in[i];
    for (int i = i0; i < NN * 384; i += gs) g_v[i] = v_in[i];
    for (int i = i0; i < NN * 3; i += gs)   out[OFFP + i] = p_in[i];
    for (int i = i0; i < EE * 32; i += gs)  out[OFFE + i] = ee_in[i];
    for (int i = i0; i < NN; i += gs)       g_cnt[i] = 0.f;
}

__global__ void k_count(const int* __restrict__ tgt) {
    int i = blockIdx.x * blockDim.x + threadIdx.x;
    if (i < EE) atomicAdd(&g_cnt[tgt[i]], 1.0f);
}
__global__ void k_icnt() {
    int i = blockIdx.x * blockDim.x + threadIdx.x;
    if (i < NN) g_icnt[i] = 1.0f / fmaxf(g_cnt[i], 1.0f);
}

__global__ void k_tail(const float* __restrict__ ed, const float* __restrict__ ea,
                       const float* __restrict__ ee, const float* __restrict__ ohe,
                       const float* __restrict__ eg) {
    int idx = blockIdx.x * blockDim.x + threadIdx.x;
    if (idx >= EE * TAILD) return;
    int e = idx / TAILD;
    int j = idx - e * TAILD;
    float val;
    if (j < 20) {
        float d = ed[e];
        float mu = (5.0f / 19.0f) * (float)j;
        float diff = d - mu;
        float env = (d < 5.0f) ? 0.5f * (cosf(3.14159265358979f * d * 0.2f) + 1.0f) : 0.0f;
        val = expf(-8.0f * diff * diff) * env;
    } else if (j == 20) val = ea[e];
    else if (j < 53)    val = ee[e * 32 + (j - 21)];
    else if (j < 56)    val = ohe[e * 3 + (j - 53)];
    else                val = eg[e * 32 + (j - 56)];
    g_tail[idx] = val;
}

// ---------------- per-node prep / final ----------------
__global__ void k_prep(const float* __restrict__ gamma, const float* __restrict__ beta) {
    __shared__ float red[256];
    int n = blockIdx.x, t = threadIdx.x;
    size_t sb = (size_t)n * SD;
    float x = g_s[sb + t];
    float mu = blockReduceSum(x, red) * (1.f / 256.f);
    float d = x - mu;
    float var = blockReduceSum(d * d, red) * (1.f / 256.f);
    float rstd = rsqrtf(var + 1e-6f);
    g_s[sb + t] = d * rstd * gamma[t] + beta[t];

    size_t vb = (size_t)n * 384;
    float v0 = g_v[vb + t];
    float v1 = (t < 128) ? g_v[vb + 256 + t] : 0.f;
    float msq = blockReduceSum(v0 * v0 + v1 * v1, red) * (1.f / 128.f);
    float rs = rsqrtf(msq + 1e-6f);
    g_v[vb + t] = v0 * rs;
    if (t < 128) g_v[vb + 256 + t] = v1 * rs;

    g_sacc[sb + t] = 0.f;
    g_vacc[vb + t] = 0.f;
    if (t < 128) g_vacc[vb + 256 + t] = 0.f;
}

__global__ void k_final(const float* __restrict__ gamma, const float* __restrict__ beta,
                        float* __restrict__ outs, float* __restrict__ outv) {
    __shared__ float red[256];
    int n = blockIdx.x, t = threadIdx.x;
    size_t sb = (size_t)n * SD;
    float x = g_s[sb + t];
    float mu = blockReduceSum(x, red) * (1.f / 256.f);
    float d = x - mu;
    float var = blockReduceSum(d * d, red) * (1.f / 256.f);
    float rstd = rsqrtf(var + 1e-6f);
    outs[sb + t] = d * rstd * gamma[t] + beta[t];

    size_t vb = (size_t)n * 384;
    float v0 = g_v[vb + t];
    float v1 = (t < 128) ? g_v[vb + 256 + t] : 0.f;
    float msq = blockReduceSum(v0 * v0 + v1 * v1, red) * (1.f / 128.f);
    float rs = rsqrtf(msq + 1e-6f);
    outv[vb + t] = v0 * rs;
    if (t < 128) outv[vb + 256 + t] = v1 * rs;
}

// ======================= edge GEMM1: h = silu(feat @ We1 + be1) =======================
// 64 edges x 256 out, K=600, BK=24, 25 double-buffered stages.
// Thread (tr=tid>>4, tc=tid&15) owns rows tr*4..+3, column pairs c=tc*2+j*32 (j=0..7).
#define G1_BK 24
#define G1_NS 25
#define G1_SMEM ((2*G1_BK*256 + 2*G1_BK*68 + 128) * 4)

__global__ __launch_bounds__(256) void k_gemm1(const int* __restrict__ src, const int* __restrict__ tgt,
                                               const float* __restrict__ W, const float* __restrict__ bias) {
    extern __shared__ float sm[];
    float* Bs = sm;                       // [2][24][256]
    float* As = sm + 2 * G1_BK * 256;     // [2][24][68]
    int* s_src = (int*)(As + 2 * G1_BK * 68);
    int* s_tgt = s_src + 64;

    const int e0 = blockIdx.x * 64;
    const int tid = threadIdx.x;
    if (tid < 64) { s_src[tid] = src[e0 + tid]; s_tgt[tid] = tgt[e0 + tid]; }
    __syncthreads();
    const int tr = tid >> 4, tc = tid & 15;
    const int ea = tid >> 2, q = tid & 3;
    const float* srow = &g_s[(size_t)s_src[ea] * SD];
    const float* trow = &g_s[(size_t)s_tgt[ea] * SD];
    const float* tailrow = &g_tail[(size_t)(e0 + ea) * TAILD];

    // prologue: stage 0 (k in [0,24) -> all from s[src])
    {
#pragma unroll
        for (int h = 0; h < 3; h++) {
            int kk = q * 6 + h * 2;
            float2 f = *(const float2*)&srow[kk];
            As[kk * 68 + ea] = f.x; As[(kk + 1) * 68 + ea] = f.y;
        }
#pragma unroll
        for (int t = 0; t < 6; t++) {
            int ci = tid + t * 256; int kk = ci >> 6, c4 = ci & 63;
            cpasync16(&Bs[kk * 256 + c4 * 4], &W[(size_t)kk * SD + c4 * 4]);
        }
        CP_COMMIT;
    }

    ull acc[4][8];
#pragma unroll
    for (int r = 0; r < 4; r++)
#pragma unroll
        for (int j = 0; j < 8; j++) acc[r][j] = 0ull;

    float2 ra[3];
    for (int s = 0; s < G1_NS; s++) {
        const int buf = s & 1;
        if (s + 1 < G1_NS) {
            int k0 = (s + 1) * G1_BK;
#pragma unroll
            for (int h = 0; h < 3; h++) {
                int k = k0 + q * 6 + h * 2;
                const float* p;
                if (k < 256)      p = &srow[k];
                else if (k < 512) p = &trow[k - 256];
                else              p = &tailrow[k - 512];
                ra[h] = *(const float2*)p;
            }
            int bb = (buf ^ 1) * G1_BK * 256;
#pragma unroll
            for (int t = 0; t < 6; t++) {
                int ci = tid + t * 256; int kk = ci >> 6, c4 = ci & 63;
                cpasync16(&Bs[bb + kk * 256 + c4 * 4], &W[(size_t)(k0 + kk) * SD + c4 * 4]);
            }
            CP_COMMIT; CP_WAIT1;
        } else {
            CP_WAIT0;
        }
        __syncthreads();

        const float* Ab = &As[buf * G1_BK * 68];
        const float* Bb = &Bs[buf * G1_BK * 256];
#pragma unroll
        for (int kk = 0; kk < G1_BK; kk++) {
            float4 av = *(const float4*)&Ab[kk * 68 + tr * 4];
            ull a0 = pk2(av.x, av.x), a1 = pk2(av.y, av.y), a2 = pk2(av.z, av.z), a3 = pk2(av.w, av.w);
#pragma unroll
            for (int j = 0; j < 8; j++) {
                ull b = *(const ull*)&Bb[kk * 256 + tc * 2 + j * 32];
                acc[0][j] = fma2(a0, b, acc[0][j]);
                acc[1][j] = fma2(a1, b, acc[1][j]);
                acc[2][j] = fma2(a2, b, acc[2][j]);
                acc[3][j] = fma2(a3, b, acc[3][j]);
            }
        }
        if (s + 1 < G1_NS) {
            int ab = (buf ^ 1) * G1_BK * 68;
#pragma unroll
            for (int h = 0; h < 3; h++) {
                int kk = q * 6 + h * 2;
                As[ab + kk * 68 + ea] = ra[h].x; As[ab + (kk + 1) * 68 + ea] = ra[h].y;
            }
        }
        __syncthreads();
    }

#pragma unroll
    for (int r = 0; r < 4; r++) {
        float* hrow = &g_h[(size_t)(e0 + tr * 4 + r) * SD];
#pragma unroll
        for (int j = 0; j < 8; j++) {
            int c = tc * 2 + j * 32;
            float2 m = upk(acc[r][j]);
            float x0 = m.x + bias[c], x1 = m.y + bias[c + 1];
            *(float2*)&hrow[c] = make_float2(siluf(x0), siluf(x1));
        }
    }
}

// ======================= edge GEMM2 + scatter =======================
// by=0: ms (cols 0..255) -> atomics to g_sacc[tgt]
// by=1: gr|gv (cols 256..511); thread owns gr[d] (j<4) and gv[d] (j>=4) -> 3 atomics/(e,d)
#define G2_BK 32
#define G2_NS 8
#define G2_SMEM ((2*G2_BK*256 + 2*G2_BK*68 + 128) * 4)

__global__ __launch_bounds__(256) void k_gemm2(const float* __restrict__ W, const float* __restrict__ bias,
                                               const int* __restrict__ src, const int* __restrict__ tgt,
                                               const float* __restrict__ rnorm) {
    extern __shared__ float sm[];
    float* Bs = sm;                       // [2][32][256]
    float* As = sm + 2 * G2_BK * 256;     // [2][32][68]
    int* s_src = (int*)(As + 2 * G2_BK * 68);
    int* s_tgt = s_src + 64;

    const int e0 = blockIdx.x * 64;
    const int by = blockIdx.y;
    const int tid = threadIdx.x;
    if (tid < 64) { s_src[tid] = src[e0 + tid]; s_tgt[tid] = tgt[e0 + tid]; }
    __syncthreads();
    const int tr = tid >> 4, tc = tid & 15;
    const int ea = tid >> 2, q = tid & 3;
    const float* arow = &g_h[(size_t)(e0 + ea) * SD];
    const float* wcol = W + by * 256;

    {
#pragma unroll
        for (int h = 0; h < 2; h++) {
            int kk = q * 8 + h * 4;
            float4 f = *(const float4*)&arow[kk];
            As[kk * 68 + ea] = f.x; As[(kk + 1) * 68 + ea] = f.y;
            As[(kk + 2) * 68 + ea] = f.z; As[(kk + 3) * 68 + ea] = f.w;
        }
#pragma unroll
        for (int t = 0; t < 8; t++) {
            int ci = tid + t * 256; int kk = ci >> 6, c4 = ci & 63;
            cpasync16(&Bs[kk * 256 + c4 * 4], &wcol[(size_t)kk * 512 + c4 * 4]);
        }
        CP_COMMIT;
    }

    ull acc[4][8];
#pragma unroll
    for (int r = 0; r < 4; r++)
#pragma unroll
        for (int j = 0; j < 8; j++) acc[r][j] = 0ull;

    float4 ra[2];
    for (int s = 0; s < G2_NS; s++) {
        const int buf = s & 1;
        if (s + 1 < G2_NS) {
            int k0 = (s + 1) * G2_BK;
#pragma unroll
            for (int h = 0; h < 2; h++) ra[h] = *(const float4*)&arow[k0 + q * 8 + h * 4];
            int bb = (buf ^ 1) * G2_BK * 256;
#pragma unroll
            for (int t = 0; t < 8; t++) {
                int ci = tid + t * 256; int kk = ci >> 6, c4 = ci & 63;
                cpasync16(&Bs[bb + kk * 256 + c4 * 4], &wcol[(size_t)(k0 + kk) * 512 + c4 * 4]);
            }
            CP_COMMIT; CP_WAIT1;
        } else {
            CP_WAIT0;
        }
        __syncthreads();

        const float* Ab = &As[buf * G2_BK * 68];
        const float* Bb = &Bs[buf * G2_BK * 256];
#pragma unroll
        for (int kk = 0; kk < G2_BK; kk++) {
            float4 av = *(const float4*)&Ab[kk * 68 + tr * 4];
            ull a0 = pk2(av.x, av.x), a1 = pk2(av.y, av.y), a2 = pk2(av.z, av.z), a3 = pk2(av.w, av.w);
#pragma unroll
            for (int j = 0; j < 8; j++) {
                ull b = *(const ull*)&Bb[kk * 256 + tc * 2 + j * 32];
                acc[0][j] = fma2(a0, b, acc[0][j]);
                acc[1][j] = fma2(a1, b, acc[1][j]);
                acc[2][j] = fma2(a2, b, acc[2][j]);
                acc[3][j] = fma2(a3, b, acc[3][j]);
            }
        }
        if (s + 1 < G2_NS) {
            int ab = (buf ^ 1) * G2_BK * 68;
#pragma unroll
            for (int h = 0; h < 2; h++) {
                int kk = q * 8 + h * 4;
                As[ab + kk * 68 + ea] = ra[h].x; As[ab + (kk + 1) * 68 + ea] = ra[h].y;
                As[ab + (kk + 2) * 68 + ea] = ra[h].z; As[ab + (kk + 3) * 68 + ea] = ra[h].w;
            }
        }
        __syncthreads();
    }

    const float* bl = bias + by * 256;
    if (by == 0) {
#pragma unroll
        for (int r = 0; r < 4; r++) {
            float* srw = &g_sacc[(size_t)s_tgt[tr * 4 + r] * SD];
#pragma unroll
            for (int j = 0; j < 8; j++) {
                int c = tc * 2 + j * 32;
                float2 m = upk(acc[r][j]);
                atomicAdd(&srw[c], m.x + bl[c]);
                atomicAdd(&srw[c + 1], m.y + bl[c + 1]);
            }
        }
    } else {
#pragma unroll
        for (int r = 0; r < 4; r++) {
            int l = tr * 4 + r;
            int eg = e0 + l;
            float* vrow = &g_vacc[(size_t)s_tgt[l] * 384];
            const float* vsrc = &g_v[(size_t)s_src[l] * 384];
            float rn0 = rnorm[eg * 3 + 0], rn1 = rnorm[eg * 3 + 1], rn2 = rnorm[eg * 3 + 2];
#pragma unroll
            for (int j = 0; j < 4; j++) {
                int d = tc * 2 + j * 32;
                float2 gr = upk(acc[r][j]);     gr.x += bl[d];       gr.y += bl[d + 1];
                float2 gv = upk(acc[r][j + 4]); gv.x += bl[128 + d]; gv.y += bl[128 + d + 1];
                float2 v0 = *(const float2*)&vsrc[d];
                float2 v1 = *(const float2*)&vsrc[128 + d];
                float2 v2 = *(const float2*)&vsrc[256 + d];
                atomicAdd(&vrow[d],         fmaf(gv.x, v0.x, gr.x * rn0));
                atomicAdd(&vrow[d + 1],     fmaf(gv.y, v0.y, gr.y * rn0));
                atomicAdd(&vrow[128 + d],     fmaf(gv.x, v1.x, gr.x * rn1));
                atomicAdd(&vrow[128 + d + 1], fmaf(gv.y, v1.y, gr.y * rn1));
                atomicAdd(&vrow[256 + d],     fmaf(gv.x, v2.x, gr.x * rn2));
                atomicAdd(&vrow[256 + d + 1], fmaf(gv.y, v2.y, gr.y * rn2));
            }
        }
    }
}

// ---------------- node: add averaged messages ----------------
__global__ void k_add() {
    int n = blockIdx.x, t = threadIdx.x;  // 384 threads
    float ic = g_icnt[n];
    if (t < 256) g_s[(size_t)n * SD + t] += g_sacc[(size_t)n * SD + t] * ic;
    g_v[(size_t)n * 384 + t] += g_vacc[(size_t)n * 384 + t] * ic;
}

// ---------------- node update: vv = v @ Wvu, nv = |vv| ----------------
__global__ void k_vv(const float* __restrict__ W) {
    __shared__ float vs[384];
    int n = blockIdx.x, t = threadIdx.x;  // 128 threads
    size_t vb = (size_t)n * 384;
    vs[t] = g_v[vb + t];
    vs[128 + t] = g_v[vb + 128 + t];
    vs[256 + t] = g_v[vb + 256 + t];
    __syncthreads();
    float a0 = 0.f, a1 = 0.f, a2 = 0.f;
#pragma unroll 8
    for (int k = 0; k < 128; k++) {
        float w = W[(size_t)k * 128 + t];
        a0 += vs[k] * w;
        a1 += vs[128 + k] * w;
        a2 += vs[256 + k] * w;
    }
    g_vv[vb + t] = a0;
    g_vv[vb + 128 + t] = a1;
    g_vv[vb + 256 + t] = a2;
    g_nv[(size_t)n * 128 + t] = sqrtf(a0 * a0 + a1 * a1 + a2 * a2 + 1e-6f);
}

// ======================= tiled node MLP 1: h2 = silu([s,nv] @ Wu1 + bu1) =======================
#define U1_BK 32
#define U1_NS 12
#define U1_SMEM ((2*U1_BK*256 + 2*U1_BK*68) * 4)

__global__ __launch_bounds__(256) void k_u1(const float* __restrict__ W, const float* __restrict__ b) {
    extern __shared__ float sm[];
    float* Bs = sm;                       // [2][32][256]
    float* As = sm + 2 * U1_BK * 256;     // [2][32][68]

    const int n0 = blockIdx.x * 64;
    const int tid = threadIdx.x;
    const int tr = tid >> 4, tc = tid & 15;
    const int ea = tid >> 2, q = tid & 3;
    int na = n0 + ea; if (na >= NN) na = NN - 1;
    const float* srow = &g_s[(size_t)na * SD];
    const float* nrow = &g_nv[(size_t)na * 128];

    {
#pragma unroll
        for (int h = 0; h < 2; h++) {
            int kk = q * 8 + h * 4;
            float4 f = *(const float4*)&srow[kk];
            As[kk * 68 + ea] = f.x; As[(kk + 1) * 68 + ea] = f.y;
            As[(kk + 2) * 68 + ea] = f.z; As[(kk + 3) * 68 + ea] = f.w;
        }
#pragma unroll
        for (int t = 0; t < 8; t++) {
            int ci = tid + t * 256; int kk = ci >> 6, c4 = ci & 63;
            cpasync16(&Bs[kk * 256 + c4 * 4], &W[(size_t)kk * 256 + c4 * 4]);
        }
        CP_COMMIT;
    }

    ull acc[4][8];
#pragma unroll
    for (int r = 0; r < 4; r++)
#pragma unroll
        for (int j = 0; j < 8; j++) acc[r][j] = 0ull;

    float4 ra[2];
    for (int s = 0; s < U1_NS; s++) {
        const int buf = s & 1;
        if (s + 1 < U1_NS) {
            int k0 = (s + 1) * U1_BK;
#pragma unroll
            for (int h = 0; h < 2; h++) {
                int k = k0 + q * 8 + h * 4;
                ra[h] = (k < 256) ? *(const float4*)&srow[k] : *(const float4*)&nrow[k - 256];
            }
            int bb = (buf ^ 1) * U1_BK * 256;
#pragma unroll
            for (int t = 0; t < 8; t++) {
                int ci = tid + t * 256; int kk = ci >> 6, c4 = ci & 63;
                cpasync16(&Bs[bb + kk * 256 + c4 * 4], &W[(size_t)(k0 + kk) * 256 + c4 * 4]);
            }
            CP_COMMIT; CP_WAIT1;
        } else {
            CP_WAIT0;
        }
        __syncthreads();

        const float* Ab = &As[buf * U1_BK * 68];
        const float* Bb = &Bs[buf * U1_BK * 256];
#pragma unroll
        for (int kk = 0; kk < U1_BK; kk++) {
            float4 av = *(const float4*)&Ab[kk * 68 + tr * 4];
            ull a0 = pk2(av.x, av.x), a1 = pk2(av.y, av.y), a2 = pk2(av.z, av.z), a3 = pk2(av.w, av.w);
#pragma unroll
            for (int j = 0; j < 8; j++) {
                ull bfrag = *(const ull*)&Bb[kk * 256 + tc * 2 + j * 32];
                acc[0][j] = fma2(a0, bfrag, acc[0][j]);
                acc[1][j] = fma2(a1, bfrag, acc[1][j]);
                acc[2][j] = fma2(a2, bfrag, acc[2][j]);
                acc[3][j] = fma2(a3, bfrag, acc[3][j]);
            }
        }
        if (s + 1 < U1_NS) {
            int ab = (buf ^ 1) * U1_BK * 68;
#pragma unroll
            for (int h = 0; h < 2; h++) {
                int kk = q * 8 + h * 4;
                As[ab + kk * 68 + ea] = ra[h].x; As[ab + (kk + 1) * 68 + ea] = ra[h].y;
                As[ab + (kk + 2) * 68 + ea] = ra[h].z; As[ab + (kk + 3) * 68 + ea] = ra[h].w;
            }
        }
        __syncthreads();
    }

#pragma unroll
    for (int r = 0; r < 4; r++) {
        int n = n0 + tr * 4 + r;
        if (n >= NN) continue;
        float* hrow = &g_h2[(size_t)n * SD];
#pragma unroll
        for (int j = 0; j < 8; j++) {
            int c = tc * 2 + j * 32;
            float2 m = upk(acc[r][j]);
            float x0 = m.x + b[c], x1 = m.y + b[c + 1];
            *(float2*)&hrow[c] = make_float2(siluf(x0), siluf(x1));
        }
    }
}

// ======================= tiled node MLP 2: u = h2 @ Wu2 + bu2; apply =======================
// grid.y in {0,1,2}: 128-col panels of the 384 outputs. y<2 -> s update; y=2 -> v update.
#define U2_BK 32
#define U2_NS 8
#define U2_SMEM ((2*U2_BK*128 + 2*U2_BK*68) * 4)

__global__ __launch_bounds__(256) void k_u2(const float* __restrict__ W, const float* __restrict__ b) {
    extern __shared__ float sm[];
    float* Bs = sm;                       // [2][32][128]
    float* As = sm + 2 * U2_BK * 128;     // [2][32][68]

    const int n0 = blockIdx.x * 64;
    const int gy = blockIdx.y;
    const int tid = threadIdx.x;
    const int tr = tid >> 4, tc = tid & 15;
    const int ea = tid >> 2, q = tid & 3;
    int na = n0 + ea; if (na >= NN) na = NN - 1;
    const float* arow = &g_h2[(size_t)na * SD];
    const float* wcol = W + gy * 128;

    {
#pragma unroll
        for (int h = 0; h < 2; h++) {
            int kk = q * 8 + h * 4;
            float4 f = *(const float4*)&arow[kk];
            As[kk * 68 + ea] = f.x; As[(kk + 1) * 68 + ea] = f.y;
            As[(kk + 2) * 68 + ea] = f.z; As[(kk + 3) * 68 + ea] = f.w;
        }
#pragma unroll
        for (int t = 0; t < 4; t++) {
            int ci = tid + t * 256; int kk = ci >> 5, c4 = ci & 31;
            cpasync16(&Bs[kk * 128 + c4 * 4], &wcol[(size_t)kk * 384 + c4 * 4]);
        }
        CP_COMMIT;
    }

    ull acc[4][4];
#pragma unroll
    for (int r = 0; r < 4; r++)
#pragma unroll
        for (int j = 0; j < 4; j++) acc[r][j] = 0ull;

    float4 ra[2];
    for (int s = 0; s < U2_NS; s++) {
        const int buf = s & 1;
        if (s + 1 < U2_NS) {
            int k0 = (s + 1) * U2_BK;
#pragma unroll
            for (int h = 0; h < 2; h++) ra[h] = *(const float4*)&arow[k0 + q * 8 + h * 4];
            int bb = (buf ^ 1) * U2_BK * 128;
#pragma unroll
            for (int t = 0; t < 4; t++) {
                int ci = tid + t * 256; int kk = ci >> 5, c4 = ci & 31;
                cpasync16(&Bs[bb + kk * 128 + c4 * 4], &wcol[(size_t)(k0 + kk) * 384 + c4 * 4]);
            }
            CP_COMMIT; CP_WAIT1;
        } else {
            CP_WAIT0;
        }
        __syncthreads();

        const float* Ab = &As[buf * U2_BK * 68];
        const float* Bb = &Bs[buf * U2_BK * 128];
#pragma unroll
        for (int kk = 0; kk < U2_BK; kk++) {
            float4 av = *(const float4*)&Ab[kk * 68 + tr * 4];
            ull a0 = pk2(av.x, av.x), a1 = pk2(av.y, av.y), a2 = pk2(av.z, av.z), a3 = pk2(av.w, av.w);
#pragma unroll
            for (int j = 0; j < 4; j++) {
                ull bfrag = *(const ull*)&Bb[kk * 128 + tc * 2 + j * 32];
                acc[0][j] = fma2(a0, bfrag, acc[0][j]);
                acc[1][j] = fma2(a1, bfrag, acc[1][j]);
                acc[2][j] = fma2(a2, bfrag, acc[2][j]);
                acc[3][j] = fma2(a3, bfrag, acc[3][j]);
            }
        }
        if (s + 1 < U2_NS) {
            int ab = (buf ^ 1) * U2_BK * 68;
#pragma unroll
            for (int h = 0; h < 2; h++) {
                int kk = q * 8 + h * 4;
                As[ab + kk * 68 + ea] = ra[h].x; As[ab + (kk + 1) * 68 + ea] = ra[h].y;
                As[ab + (kk + 2) * 68 + ea] = ra[h].z; As[ab + (kk + 3) * 68 + ea] = ra[h].w;
            }
        }
        __syncthreads();
    }

#pragma unroll
    for (int r = 0; r < 4; r++) {
        int n = n0 + tr * 4 + r;
        if (n >= NN) continue;
#pragma unroll
        for (int j = 0; j < 4; j++) {
            int c = tc * 2 + j * 32;
            int cg = gy * 128 + c;
            float2 m = upk(acc[r][j]);
            m.x += b[cg]; m.y += b[cg + 1];
            if (gy < 2) {
                g_s[(size_t)n * SD + cg] += m.x;
                g_s[(size_t)n * SD + cg + 1] += m.y;
            } else {
                size_t vb = (size_t)n * 384;
#pragma unroll
                for (int cc = 0; cc < 3; cc++) {
                    g_v[vb + cc * 128 + c]     += g_vv[vb + cc * 128 + c] * m.x;
                    g_v[vb + cc * 128 + c + 1] += g_vv[vb + cc * 128 + c + 1] * m.y;
                }
            }
        }
    }
}

// ---------------- launch ----------------
extern "C" void kernel_launch(void* const* d_in, const int* in_sizes, int n_in,
                              void* d_out, int out_size) {
    const float* s_in   = (const float*)d_in[0];
    const float* v_in   = (const float*)d_in[1];
    const float* p_in   = (const float*)d_in[2];
    const int*   eidx   = (const int*)d_in[3];
    const float* edge_d = (const float*)d_in[4];
    const float* edge_a = (const float*)d_in[5];
    const float* rnorm  = (const float*)d_in[6];
    const float* edge_e = (const float*)d_in[7];
    const float* ohe    = (const float*)d_in[8];
    const float* eglob  = (const float*)d_in[9];
    const float* gamma  = (const float*)d_in[10];
    const float* beta   = (const float*)d_in[11];
    const float* We1    = (const float*)d_in[12];
    const float* be1    = (const float*)d_in[13];
    const float* We2    = (const float*)d_in[14];
    const float* be2    = (const float*)d_in[15];
    const float* Wvu    = (const float*)d_in[16];
    const float* Wu1    = (const float*)d_in[17];
    const float* bu1    = (const float*)d_in[18];
    const float* Wu2    = (const float*)d_in[19];
    const float* bu2    = (const float*)d_in[20];

    const int* src = eidx;
    const int* tgt = eidx + EE;
    float* out = (float*)d_out;

    cudaFuncSetAttribute(k_gemm1, cudaFuncAttributeMaxDynamicSharedMemorySize, G1_SMEM);
    cudaFuncSetAttribute(k_gemm2, cudaFuncAttributeMaxDynamicSharedMemorySize, G2_SMEM);
    cudaFuncSetAttribute(k_u1,    cudaFuncAttributeMaxDynamicSharedMemorySize, U1_SMEM);
    cudaFuncSetAttribute(k_u2,    cudaFuncAttributeMaxDynamicSharedMemorySize, U2_SMEM);

    k_init<<<2048, 256>>>(s_in, v_in, p_in, edge_e, out);
    k_count<<<(EE + 255) / 256, 256>>>(tgt);
    k_icnt<<<(NN + 255) / 256, 256>>>();
    k_tail<<<(EE * TAILD + 255) / 256, 256>>>(edge_d, edge_a, edge_e, ohe, eglob);

    const int NBLK = (NN + 63) / 64;  // 157
    for (int i = 0; i < 5; i++) {
        k_prep<<<NN, 256>>>(gamma + i * 256, beta + i * 256);
        k_gemm1<<<EE / 64, 256, G1_SMEM>>>(src, tgt, We1 + (size_t)i * 600 * SD, be1 + i * 256);
        k_gemm2<<<dim3(EE / 64, 2), 256, G2_SMEM>>>(We2 + (size_t)i * SD * 512, be2 + i * 512, src, tgt, rnorm);
        k_add<<<NN, 384>>>();
        if (i < 4) {
            k_vv<<<NN, 128>>>(Wvu + (size_t)i * 128 * 128);
            k_u1<<<NBLK, 256, U1_SMEM>>>(Wu1 + (size_t)i * 384 * 256, bu1 + i * 256);
            k_u2<<<dim3(NBLK, 3), 256, U2_SMEM>>>(Wu2 + (size_t)i * 256 * 384, bu2 + i * 384);
        }
    }
    k_final<<<NN, 256>>>(gamma + 5 * 256, beta + 5 * 256, out, out + OFFV);
}

// round 6
// speedup vs baseline: 4.9670x; 1.4498x over previous
#include <cuda_runtime.h>
#include <math.h>

#define NN 10000
#define EE 160000
#define SD 256
#define TAILD 88

#define OFFV 2560000   // N*256
#define OFFP 6400000   // +N*384
#define OFFE 6430000   // +N*3

typedef unsigned long long ull;

// ---------------- device scratch (no allocations allowed) ----------------
__device__ __align__(16) float g_s[NN * SD];
__device__ __align__(16) float g_v[NN * 384];
__device__ __align__(16) float g_sacc[NN * SD];
__device__ __align__(16) float g_vacc[NN * 384];
__device__ __align__(16) float g_h[(size_t)EE * SD];
__device__ __align__(16) float g_tail[(size_t)EE * TAILD];
__device__ __align__(16) float g_vv[NN * 384];
__device__ __align__(16) float g_nv[NN * 128];
__device__ __align__(16) float g_h2[NN * SD];
__device__ __align__(16) float g_csrc[NN * SD];
__device__ __align__(16) float g_ctgt[NN * SD];
__device__ float g_cnt[NN];
__device__ float g_icnt[NN];

// ---------------- helpers ----------------
__device__ __forceinline__ ull pk2(float lo, float hi) {
    ull r; asm("mov.b64 %0, {%1,%2};" : "=l"(r) : "f"(lo), "f"(hi)); return r;
}
__device__ __forceinline__ ull fma2(ull a, ull b, ull c) {
    ull d; asm("fma.rn.f32x2 %0, %1, %2, %3;" : "=l"(d) : "l"(a), "l"(b), "l"(c)); return d;
}
__device__ __forceinline__ float2 upk(ull x) {
    float2 f; asm("mov.b64 {%0,%1}, %2;" : "=f"(f.x), "=f"(f.y) : "l"(x)); return f;
}
__device__ __forceinline__ float siluf(float x) { return x / (1.f + __expf(-x)); }

__device__ __forceinline__ void cpasync16(void* sdst, const void* gsrc) {
    unsigned sa = (unsigned)__cvta_generic_to_shared(sdst);
    asm volatile("cp.async.cg.shared.global [%0], [%1], 16;" :: "r"(sa), "l"(gsrc));
}
#define CP_COMMIT asm volatile("cp.async.commit_group;")
#define CP_WAIT1  asm volatile("cp.async.wait_group 1;" ::: "memory")
#define CP_WAIT0  asm volatile("cp.async.wait_group 0;" ::: "memory")

__device__ __forceinline__ float blockReduceSum(float v, float* red) {
    int t = threadIdx.x;
    red[t] = v; __syncthreads();
    for (int s = blockDim.x >> 1; s > 0; s >>= 1) {
        if (t < s) red[t] += red[t + s];
        __syncthreads();
    }
    float r = red[0]; __syncthreads();
    return r;
}

// ---------------- init / counts / tail ----------------
__global__ void k_init(const float* __restrict__ s_in, const float* __restrict__ v_in,
                       const float* __restrict__ p_in, const float* __restrict__ ee_in,
                       float* __restrict__ out) {
    int gs = gridDim.x * blockDim.x;
    int i0 = blockIdx.x * blockDim.x + threadIdx.x;
    for (int i = i0; i < NN * SD; i += gs)  g_s[i] = s_in[i];
    for (int i = i0; i < NN * 384; i += gs) g_v[i] = v_in[i];
    for (int i = i0; i < NN * 3; i += gs)   out[OFFP + i] = p_in[i];
    for (int i = i0; i < EE * 32; i += gs)  out[OFFE + i] = ee_in[i];
    for (int i = i0; i < NN; i += gs)       g_cnt[i] = 0.f;
}

__global__ void k_count(const int* __restrict__ tgt) {
    int i = blockIdx.x * blockDim.x + threadIdx.x;
    if (i < EE) atomicAdd(&g_cnt[tgt[i]], 1.0f);
}
__global__ void k_icnt() {
    int i = blockIdx.x * blockDim.x + threadIdx.x;
    if (i < NN) g_icnt[i] = 1.0f / fmaxf(g_cnt[i], 1.0f);
}

__global__ void k_tail(const float* __restrict__ ed, const float* __restrict__ ea,
                       const float* __restrict__ ee, const float* __restrict__ ohe,
                       const float* __restrict__ eg) {
    int idx = blockIdx.x * blockDim.x + threadIdx.x;
    if (idx >= EE * TAILD) return;
    int e = idx / TAILD;
    int j = idx - e * TAILD;
    float val;
    if (j < 20) {
        float d = ed[e];
        float mu = (5.0f / 19.0f) * (float)j;
        float diff = d - mu;
        float env = (d < 5.0f) ? 0.5f * (cosf(3.14159265358979f * d * 0.2f) + 1.0f) : 0.0f;
        val = expf(-8.0f * diff * diff) * env;
    } else if (j == 20) val = ea[e];
    else if (j < 53)    val = ee[e * 32 + (j - 21)];
    else if (j < 56)    val = ohe[e * 3 + (j - 53)];
    else                val = eg[e * 32 + (j - 56)];
    g_tail[idx] = val;
}

// ---------------- per-node prep / final ----------------
__global__ void k_prep(const float* __restrict__ gamma, const float* __restrict__ beta) {
    __shared__ float red[256];
    int n = blockIdx.x, t = threadIdx.x;
    size_t sb = (size_t)n * SD;
    float x = g_s[sb + t];
    float mu = blockReduceSum(x, red) * (1.f / 256.f);
    float d = x - mu;
    float var = blockReduceSum(d * d, red) * (1.f / 256.f);
    float rstd = rsqrtf(var + 1e-6f);
    g_s[sb + t] = d * rstd * gamma[t] + beta[t];

    size_t vb = (size_t)n * 384;
    float v0 = g_v[vb + t];
    float v1 = (t < 128) ? g_v[vb + 256 + t] : 0.f;
    float msq = blockReduceSum(v0 * v0 + v1 * v1, red) * (1.f / 128.f);
    float rs = rsqrtf(msq + 1e-6f);
    g_v[vb + t] = v0 * rs;
    if (t < 128) g_v[vb + 256 + t] = v1 * rs;

    g_sacc[sb + t] = 0.f;
    g_vacc[vb + t] = 0.f;
    if (t < 128) g_vacc[vb + 256 + t] = 0.f;
}

__global__ void k_final(const float* __restrict__ gamma, const float* __restrict__ beta,
                        float* __restrict__ outs, float* __restrict__ outv) {
    __shared__ float red[256];
    int n = blockIdx.x, t = threadIdx.x;
    size_t sb = (size_t)n * SD;
    float x = g_s[sb + t];
    float mu = blockReduceSum(x, red) * (1.f / 256.f);
    float d = x - mu;
    float var = blockReduceSum(d * d, red) * (1.f / 256.f);
    float rstd = rsqrtf(var + 1e-6f);
    outs[sb + t] = d * rstd * gamma[t] + beta[t];

    size_t vb = (size_t)n * 384;
    float v0 = g_v[vb + t];
    float v1 = (t < 128) ? g_v[vb + 256 + t] : 0.f;
    float msq = blockReduceSum(v0 * v0 + v1 * v1, red) * (1.f / 128.f);
    float rs = rsqrtf(msq + 1e-6f);
    outv[vb + t] = v0 * rs;
    if (t < 128) outv[vb + 256 + t] = v1 * rs;
}

// ======================= node precompute: c_{src,tgt} = s @ We1[gy*256 : gy*256+256] =======================
// grid (ceil(N/64), 2); 64 nodes x 256 out per block; K=256, BK=32, 8 stages.
#define CM_BK 32
#define CM_NS 8
#define CM_SMEM ((2*CM_BK*256 + 2*CM_BK*68) * 4)

__global__ __launch_bounds__(256) void k_cmm(const float* __restrict__ W) {
    extern __shared__ float sm[];
    float* Bs = sm;                       // [2][32][256]
    float* As = sm + 2 * CM_BK * 256;     // [2][32][68]

    const int n0 = blockIdx.x * 64;
    const int gy = blockIdx.y;
    const int tid = threadIdx.x;
    const int tr = tid >> 4, tc = tid & 15;
    const int ea = tid >> 2, q = tid & 3;
    int na = n0 + ea; if (na >= NN) na = NN - 1;
    const float* srow = &g_s[(size_t)na * SD];
    const float* Wb = W + (size_t)gy * 256 * SD;   // row gy*256 of We1 (row stride 256)
    float* outb = gy ? g_ctgt : g_csrc;

    {
#pragma unroll
        for (int h = 0; h < 2; h++) {
            int kk = q * 8 + h * 4;
            float4 f = *(const float4*)&srow[kk];
            As[kk * 68 + ea] = f.x; As[(kk + 1) * 68 + ea] = f.y;
            As[(kk + 2) * 68 + ea] = f.z; As[(kk + 3) * 68 + ea] = f.w;
        }
#pragma unroll
        for (int t = 0; t < 8; t++) {
            int ci = tid + t * 256; int kk = ci >> 6, c4 = ci & 63;
            cpasync16(&Bs[kk * 256 + c4 * 4], &Wb[(size_t)kk * SD + c4 * 4]);
        }
        CP_COMMIT;
    }

    ull acc[4][8];
#pragma unroll
    for (int r = 0; r < 4; r++)
#pragma unroll
        for (int j = 0; j < 8; j++) acc[r][j] = 0ull;

    float4 ra[2];
    for (int s = 0; s < CM_NS; s++) {
        const int buf = s & 1;
        if (s + 1 < CM_NS) {
            int k0 = (s + 1) * CM_BK;
#pragma unroll
            for (int h = 0; h < 2; h++) ra[h] = *(const float4*)&srow[k0 + q * 8 + h * 4];
            int bb = (buf ^ 1) * CM_BK * 256;
#pragma unroll
            for (int t = 0; t < 8; t++) {
                int ci = tid + t * 256; int kk = ci >> 6, c4 = ci & 63;
                cpasync16(&Bs[bb + kk * 256 + c4 * 4], &Wb[(size_t)(k0 + kk) * SD + c4 * 4]);
            }
            CP_COMMIT; CP_WAIT1;
        } else {
            CP_WAIT0;
        }
        __syncthreads();

        const float* Ab = &As[buf * CM_BK * 68];
        const float* Bb = &Bs[buf * CM_BK * 256];
#pragma unroll
        for (int kk = 0; kk < CM_BK; kk++) {
            float4 av = *(const float4*)&Ab[kk * 68 + tr * 4];
            ull a0 = pk2(av.x, av.x), a1 = pk2(av.y, av.y), a2 = pk2(av.z, av.z), a3 = pk2(av.w, av.w);
#pragma unroll
            for (int j = 0; j < 8; j++) {
                ull b = *(const ull*)&Bb[kk * 256 + tc * 2 + j * 32];
                acc[0][j] = fma2(a0, b, acc[0][j]);
                acc[1][j] = fma2(a1, b, acc[1][j]);
                acc[2][j] = fma2(a2, b, acc[2][j]);
                acc[3][j] = fma2(a3, b, acc[3][j]);
            }
        }
        if (s + 1 < CM_NS) {
            int ab = (buf ^ 1) * CM_BK * 68;
#pragma unroll
            for (int h = 0; h < 2; h++) {
                int kk = q * 8 + h * 4;
                As[ab + kk * 68 + ea] = ra[h].x; As[ab + (kk + 1) * 68 + ea] = ra[h].y;
                As[ab + (kk + 2) * 68 + ea] = ra[h].z; As[ab + (kk + 3) * 68 + ea] = ra[h].w;
            }
        }
        __syncthreads();
    }

#pragma unroll
    for (int r = 0; r < 4; r++) {
        int n = n0 + tr * 4 + r;
        if (n >= NN) continue;
        float* orow = &outb[(size_t)n * SD];
#pragma unroll
        for (int j = 0; j < 8; j++) {
            int c = tc * 2 + j * 32;
            float2 m = upk(acc[r][j]);
            *(float2*)&orow[c] = m;
        }
    }
}

// ======================= edge kernel 1: h = silu(c_src[src] + c_tgt[tgt] + tail@Wt + be1) =======================
// 64 edges x 256 out, K=88, BK=8, 11 double-buffered stages.
#define E1_BK 8
#define E1_NS 11
#define E1_SMEM ((2*E1_BK*256 + 2*E1_BK*68 + 128) * 4)

__global__ __launch_bounds__(256) void k_edge1(const int* __restrict__ src, const int* __restrict__ tgt,
                                               const float* __restrict__ Wt, const float* __restrict__ bias) {
    extern __shared__ float sm[];
    float* Bs = sm;                       // [2][8][256]
    float* As = sm + 2 * E1_BK * 256;     // [2][8][68]
    int* s_src = (int*)(As + 2 * E1_BK * 68);
    int* s_tgt = s_src + 64;

    const int e0 = blockIdx.x * 64;
    const int tid = threadIdx.x;
    if (tid < 64) { s_src[tid] = src[e0 + tid]; s_tgt[tid] = tgt[e0 + tid]; }
    __syncthreads();
    const int tr = tid >> 4, tc = tid & 15;
    const int ea = tid >> 2, q = tid & 3;
    const float* tailrow = &g_tail[(size_t)(e0 + ea) * TAILD];

    // prologue stage 0 (k in [0,8))
    {
        int kk = q * 2;
        float2 f = *(const float2*)&tailrow[kk];
        As[kk * 68 + ea] = f.x; As[(kk + 1) * 68 + ea] = f.y;
#pragma unroll
        for (int t = 0; t < 2; t++) {
            int ci = tid + t * 256; int kk2 = ci >> 6, c4 = ci & 63;
            cpasync16(&Bs[kk2 * 256 + c4 * 4], &Wt[(size_t)kk2 * SD + c4 * 4]);
        }
        CP_COMMIT;
    }

    ull acc[4][8];
#pragma unroll
    for (int r = 0; r < 4; r++)
#pragma unroll
        for (int j = 0; j < 8; j++) acc[r][j] = 0ull;

    float2 ra;
    for (int s = 0; s < E1_NS; s++) {
        const int buf = s & 1;
        if (s + 1 < E1_NS) {
            int k0 = (s + 1) * E1_BK;
            ra = *(const float2*)&tailrow[k0 + q * 2];
            int bb = (buf ^ 1) * E1_BK * 256;
#pragma unroll
            for (int t = 0; t < 2; t++) {
                int ci = tid + t * 256; int kk2 = ci >> 6, c4 = ci & 63;
                cpasync16(&Bs[bb + kk2 * 256 + c4 * 4], &Wt[(size_t)(k0 + kk2) * SD + c4 * 4]);
            }
            CP_COMMIT; CP_WAIT1;
        } else {
            CP_WAIT0;
        }
        __syncthreads();

        const float* Ab = &As[buf * E1_BK * 68];
        const float* Bb = &Bs[buf * E1_BK * 256];
#pragma unroll
        for (int kk = 0; kk < E1_BK; kk++) {
            float4 av = *(const float4*)&Ab[kk * 68 + tr * 4];
            ull a0 = pk2(av.x, av.x), a1 = pk2(av.y, av.y), a2 = pk2(av.z, av.z), a3 = pk2(av.w, av.w);
#pragma unroll
            for (int j = 0; j < 8; j++) {
                ull b = *(const ull*)&Bb[kk * 256 + tc * 2 + j * 32];
                acc[0][j] = fma2(a0, b, acc[0][j]);
                acc[1][j] = fma2(a1, b, acc[1][j]);
                acc[2][j] = fma2(a2, b, acc[2][j]);
                acc[3][j] = fma2(a3, b, acc[3][j]);
            }
        }
        if (s + 1 < E1_NS) {
            int ab = (buf ^ 1) * E1_BK * 68;
            int kk = q * 2;
            As[ab + kk * 68 + ea] = ra.x; As[ab + (kk + 1) * 68 + ea] = ra.y;
        }
        __syncthreads();
    }

    // epilogue: gather per-node contributions, bias, silu, store
#pragma unroll
    for (int r = 0; r < 4; r++) {
        int l = tr * 4 + r;
        const float* csrow = &g_csrc[(size_t)s_src[l] * SD];
        const float* ctrow = &g_ctgt[(size_t)s_tgt[l] * SD];
        float* hrow = &g_h[(size_t)(e0 + l) * SD];
#pragma unroll
        for (int j = 0; j < 8; j++) {
            int c = tc * 2 + j * 32;
            float2 m = upk(acc[r][j]);
            float2 a = *(const float2*)&csrow[c];
            float2 b = *(const float2*)&ctrow[c];
            float x0 = m.x + a.x + b.x + bias[c];
            float x1 = m.y + a.y + b.y + bias[c + 1];
            *(float2*)&hrow[c] = make_float2(siluf(x0), siluf(x1));
        }
    }
}

// ======================= edge GEMM2 + scatter =======================
#define G2_BK 32
#define G2_NS 8
#define G2_SMEM ((2*G2_BK*256 + 2*G2_BK*68 + 128) * 4)

__global__ __launch_bounds__(256) void k_gemm2(const float* __restrict__ W, const float* __restrict__ bias,
                                               const int* __restrict__ src, const int* __restrict__ tgt,
                                               const float* __restrict__ rnorm) {
    extern __shared__ float sm[];
    float* Bs = sm;                       // [2][32][256]
    float* As = sm + 2 * G2_BK * 256;     // [2][32][68]
    int* s_src = (int*)(As + 2 * G2_BK * 68);
    int* s_tgt = s_src + 64;

    const int e0 = blockIdx.x * 64;
    const int by = blockIdx.y;
    const int tid = threadIdx.x;
    if (tid < 64) { s_src[tid] = src[e0 + tid]; s_tgt[tid] = tgt[e0 + tid]; }
    __syncthreads();
    const int tr = tid >> 4, tc = tid & 15;
    const int ea = tid >> 2, q = tid & 3;
    const float* arow = &g_h[(size_t)(e0 + ea) * SD];
    const float* wcol = W + by * 256;

    {
#pragma unroll
        for (int h = 0; h < 2; h++) {
            int kk = q * 8 + h * 4;
            float4 f = *(const float4*)&arow[kk];
            As[kk * 68 + ea] = f.x; As[(kk + 1) * 68 + ea] = f.y;
            As[(kk + 2) * 68 + ea] = f.z; As[(kk + 3) * 68 + ea] = f.w;
        }
#pragma unroll
        for (int t = 0; t < 8; t++) {
            int ci = tid + t * 256; int kk = ci >> 6, c4 = ci & 63;
            cpasync16(&Bs[kk * 256 + c4 * 4], &wcol[(size_t)kk * 512 + c4 * 4]);
        }
        CP_COMMIT;
    }

    ull acc[4][8];
#pragma unroll
    for (int r = 0; r < 4; r++)
#pragma unroll
        for (int j = 0; j < 8; j++) acc[r][j] = 0ull;

    float4 ra[2];
    for (int s = 0; s < G2_NS; s++) {
        const int buf = s & 1;
        if (s + 1 < G2_NS) {
            int k0 = (s + 1) * G2_BK;
#pragma unroll
            for (int h = 0; h < 2; h++) ra[h] = *(const float4*)&arow[k0 + q * 8 + h * 4];
            int bb = (buf ^ 1) * G2_BK * 256;
#pragma unroll
            for (int t = 0; t < 8; t++) {
                int ci = tid + t * 256; int kk = ci >> 6, c4 = ci & 63;
                cpasync16(&Bs[bb + kk * 256 + c4 * 4], &wcol[(size_t)(k0 + kk) * 512 + c4 * 4]);
            }
            CP_COMMIT; CP_WAIT1;
        } else {
            CP_WAIT0;
        }
        __syncthreads();

        const float* Ab = &As[buf * G2_BK * 68];
        const float* Bb = &Bs[buf * G2_BK * 256];
#pragma unroll
        for (int kk = 0; kk < G2_BK; kk++) {
            float4 av = *(const float4*)&Ab[kk * 68 + tr * 4];
            ull a0 = pk2(av.x, av.x), a1 = pk2(av.y, av.y), a2 = pk2(av.z, av.z), a3 = pk2(av.w, av.w);
#pragma unroll
            for (int j = 0; j < 8; j++) {
                ull b = *(const ull*)&Bb[kk * 256 + tc * 2 + j * 32];
                acc[0][j] = fma2(a0, b, acc[0][j]);
                acc[1][j] = fma2(a1, b, acc[1][j]);
                acc[2][j] = fma2(a2, b, acc[2][j]);
                acc[3][j] = fma2(a3, b, acc[3][j]);
            }
        }
        if (s + 1 < G2_NS) {
            int ab = (buf ^ 1) * G2_BK * 68;
#pragma unroll
            for (int h = 0; h < 2; h++) {
                int kk = q * 8 + h * 4;
                As[ab + kk * 68 + ea] = ra[h].x; As[ab + (kk + 1) * 68 + ea] = ra[h].y;
                As[ab + (kk + 2) * 68 + ea] = ra[h].z; As[ab + (kk + 3) * 68 + ea] = ra[h].w;
            }
        }
        __syncthreads();
    }

    const float* bl = bias + by * 256;
    if (by == 0) {
#pragma unroll
        for (int r = 0; r < 4; r++) {
            float* srw = &g_sacc[(size_t)s_tgt[tr * 4 + r] * SD];
#pragma unroll
            for (int j = 0; j < 8; j++) {
                int c = tc * 2 + j * 32;
                float2 m = upk(acc[r][j]);
                atomicAdd(&srw[c], m.x + bl[c]);
                atomicAdd(&srw[c + 1], m.y + bl[c + 1]);
            }
        }
    } else {
#pragma unroll
        for (int r = 0; r < 4; r++) {
            int l = tr * 4 + r;
            int eg = e0 + l;
            float* vrow = &g_vacc[(size_t)s_tgt[l] * 384];
            const float* vsrc = &g_v[(size_t)s_src[l] * 384];
            float rn0 = rnorm[eg * 3 + 0], rn1 = rnorm[eg * 3 + 1], rn2 = rnorm[eg * 3 + 2];
#pragma unroll
            for (int j = 0; j < 4; j++) {
                int d = tc * 2 + j * 32;
                float2 gr = upk(acc[r][j]);     gr.x += bl[d];       gr.y += bl[d + 1];
                float2 gv = upk(acc[r][j + 4]); gv.x += bl[128 + d]; gv.y += bl[128 + d + 1];
                float2 v0 = *(const float2*)&vsrc[d];
                float2 v1 = *(const float2*)&vsrc[128 + d];
                float2 v2 = *(const float2*)&vsrc[256 + d];
                atomicAdd(&vrow[d],         fmaf(gv.x, v0.x, gr.x * rn0));
                atomicAdd(&vrow[d + 1],     fmaf(gv.y, v0.y, gr.y * rn0));
                atomicAdd(&vrow[128 + d],     fmaf(gv.x, v1.x, gr.x * rn1));
                atomicAdd(&vrow[128 + d + 1], fmaf(gv.y, v1.y, gr.y * rn1));
                atomicAdd(&vrow[256 + d],     fmaf(gv.x, v2.x, gr.x * rn2));
                atomicAdd(&vrow[256 + d + 1], fmaf(gv.y, v2.y, gr.y * rn2));
            }
        }
    }
}

// ---------------- node: add averaged messages ----------------
__global__ void k_add() {
    int n = blockIdx.x, t = threadIdx.x;  // 384 threads
    float ic = g_icnt[n];
    if (t < 256) g_s[(size_t)n * SD + t] += g_sacc[(size_t)n * SD + t] * ic;
    g_v[(size_t)n * 384 + t] += g_vacc[(size_t)n * 384 + t] * ic;
}

// ---------------- node update: vv = v @ Wvu, nv = |vv| ----------------
__global__ void k_vv(const float* __restrict__ W) {
    __shared__ float vs[384];
    int n = blockIdx.x, t = threadIdx.x;  // 128 threads
    size_t vb = (size_t)n * 384;
    vs[t] = g_v[vb + t];
    vs[128 + t] = g_v[vb + 128 + t];
    vs[256 + t] = g_v[vb + 256 + t];
    __syncthreads();
    float a0 = 0.f, a1 = 0.f, a2 = 0.f;
#pragma unroll 8
    for (int k = 0; k < 128; k++) {
        float w = W[(size_t)k * 128 + t];
        a0 += vs[k] * w;
        a1 += vs[128 + k] * w;
        a2 += vs[256 + k] * w;
    }
    g_vv[vb + t] = a0;
    g_vv[vb + 128 + t] = a1;
    g_vv[vb + 256 + t] = a2;
    g_nv[(size_t)n * 128 + t] = sqrtf(a0 * a0 + a1 * a1 + a2 * a2 + 1e-6f);
}

// ======================= tiled node MLP 1: h2 = silu([s,nv] @ Wu1 + bu1) =======================
#define U1_BK 32
#define U1_NS 12
#define U1_SMEM ((2*U1_BK*256 + 2*U1_BK*68) * 4)

__global__ __launch_bounds__(256) void k_u1(const float* __restrict__ W, const float* __restrict__ b) {
    extern __shared__ float sm[];
    float* Bs = sm;                       // [2][32][256]
    float* As = sm + 2 * U1_BK * 256;     // [2][32][68]

    const int n0 = blockIdx.x * 64;
    const int tid = threadIdx.x;
    const int tr = tid >> 4, tc = tid & 15;
    const int ea = tid >> 2, q = tid & 3;
    int na = n0 + ea; if (na >= NN) na = NN - 1;
    const float* srow = &g_s[(size_t)na * SD];
    const float* nrow = &g_nv[(size_t)na * 128];

    {
#pragma unroll
        for (int h = 0; h < 2; h++) {
            int kk = q * 8 + h * 4;
            float4 f = *(const float4*)&srow[kk];
            As[kk * 68 + ea] = f.x; As[(kk + 1) * 68 + ea] = f.y;
            As[(kk + 2) * 68 + ea] = f.z; As[(kk + 3) * 68 + ea] = f.w;
        }
#pragma unroll
        for (int t = 0; t < 8; t++) {
            int ci = tid + t * 256; int kk = ci >> 6, c4 = ci & 63;
            cpasync16(&Bs[kk * 256 + c4 * 4], &W[(size_t)kk * 256 + c4 * 4]);
        }
        CP_COMMIT;
    }

    ull acc[4][8];
#pragma unroll
    for (int r = 0; r < 4; r++)
#pragma unroll
        for (int j = 0; j < 8; j++) acc[r][j] = 0ull;

    float4 ra[2];
    for (int s = 0; s < U1_NS; s++) {
        const int buf = s & 1;
        if (s + 1 < U1_NS) {
            int k0 = (s + 1) * U1_BK;
#pragma unroll
            for (int h = 0; h < 2; h++) {
                int k = k0 + q * 8 + h * 4;
                ra[h] = (k < 256) ? *(const float4*)&srow[k] : *(const float4*)&nrow[k - 256];
            }
            int bb = (buf ^ 1) * U1_BK * 256;
#pragma unroll
            for (int t = 0; t < 8; t++) {
                int ci = tid + t * 256; int kk = ci >> 6, c4 = ci & 63;
                cpasync16(&Bs[bb + kk * 256 + c4 * 4], &W[(size_t)(k0 + kk) * 256 + c4 * 4]);
            }
            CP_COMMIT; CP_WAIT1;
        } else {
            CP_WAIT0;
        }
        __syncthreads();

        const float* Ab = &As[buf * U1_BK * 68];
        const float* Bb = &Bs[buf * U1_BK * 256];
#pragma unroll
        for (int kk = 0; kk < U1_BK; kk++) {
            float4 av = *(const float4*)&Ab[kk * 68 + tr * 4];
            ull a0 = pk2(av.x, av.x), a1 = pk2(av.y, av.y), a2 = pk2(av.z, av.z), a3 = pk2(av.w, av.w);
#pragma unroll
            for (int j = 0; j < 8; j++) {
                ull bfrag = *(const ull*)&Bb[kk * 256 + tc * 2 + j * 32];
                acc[0][j] = fma2(a0, bfrag, acc[0][j]);
                acc[1][j] = fma2(a1, bfrag, acc[1][j]);
                acc[2][j] = fma2(a2, bfrag, acc[2][j]);
                acc[3][j] = fma2(a3, bfrag, acc[3][j]);
            }
        }
        if (s + 1 < U1_NS) {
            int ab = (buf ^ 1) * U1_BK * 68;
#pragma unroll
            for (int h = 0; h < 2; h++) {
                int kk = q * 8 + h * 4;
                As[ab + kk * 68 + ea] = ra[h].x; As[ab + (kk + 1) * 68 + ea] = ra[h].y;
                As[ab + (kk + 2) * 68 + ea] = ra[h].z; As[ab + (kk + 3) * 68 + ea] = ra[h].w;
            }
        }
        __syncthreads();
    }

#pragma unroll
    for (int r = 0; r < 4; r++) {
        int n = n0 + tr * 4 + r;
        if (n >= NN) continue;
        float* hrow = &g_h2[(size_t)n * SD];
#pragma unroll
        for (int j = 0; j < 8; j++) {
            int c = tc * 2 + j * 32;
            float2 m = upk(acc[r][j]);
            float x0 = m.x + b[c], x1 = m.y + b[c + 1];
            *(float2*)&hrow[c] = make_float2(siluf(x0), siluf(x1));
        }
    }
}

// ======================= tiled node MLP 2: u = h2 @ Wu2 + bu2; apply =======================
#define U2_BK 32
#define U2_NS 8
#define U2_SMEM ((2*U2_BK*128 + 2*U2_BK*68) * 4)

__global__ __launch_bounds__(256) void k_u2(const float* __restrict__ W, const float* __restrict__ b) {
    extern __shared__ float sm[];
    float* Bs = sm;                       // [2][32][128]
    float* As = sm + 2 * U2_BK * 128;     // [2][32][68]

    const int n0 = blockIdx.x * 64;
    const int gy = blockIdx.y;
    const int tid = threadIdx.x;
    const int tr = tid >> 4, tc = tid & 15;
    const int ea = tid >> 2, q = tid & 3;
    int na = n0 + ea; if (na >= NN) na = NN - 1;
    const float* arow = &g_h2[(size_t)na * SD];
    const float* wcol = W + gy * 128;

    {
#pragma unroll
        for (int h = 0; h < 2; h++) {
            int kk = q * 8 + h * 4;
            float4 f = *(const float4*)&arow[kk];
            As[kk * 68 + ea] = f.x; As[(kk + 1) * 68 + ea] = f.y;
            As[(kk + 2) * 68 + ea] = f.z; As[(kk + 3) * 68 + ea] = f.w;
        }
#pragma unroll
        for (int t = 0; t < 4; t++) {
            int ci = tid + t * 256; int kk = ci >> 5, c4 = ci & 31;
            cpasync16(&Bs[kk * 128 + c4 * 4], &wcol[(size_t)kk * 384 + c4 * 4]);
        }
        CP_COMMIT;
    }

    ull acc[4][4];
#pragma unroll
    for (int r = 0; r < 4; r++)
#pragma unroll
        for (int j = 0; j < 4; j++) acc[r][j] = 0ull;

    float4 ra[2];
    for (int s = 0; s < U2_NS; s++) {
        const int buf = s & 1;
        if (s + 1 < U2_NS) {
            int k0 = (s + 1) * U2_BK;
#pragma unroll
            for (int h = 0; h < 2; h++) ra[h] = *(const float4*)&arow[k0 + q * 8 + h * 4];
            int bb = (buf ^ 1) * U2_BK * 128;
#pragma unroll
            for (int t = 0; t < 4; t++) {
                int ci = tid + t * 256; int kk = ci >> 5, c4 = ci & 31;
                cpasync16(&Bs[bb + kk * 128 + c4 * 4], &wcol[(size_t)(k0 + kk) * 384 + c4 * 4]);
            }
            CP_COMMIT; CP_WAIT1;
        } else {
            CP_WAIT0;
        }
        __syncthreads();

        const float* Ab = &As[buf * U2_BK * 68];
        const float* Bb = &Bs[buf * U2_BK * 128];
#pragma unroll
        for (int kk = 0; kk < U2_BK; kk++) {
            float4 av = *(const float4*)&Ab[kk * 68 + tr * 4];
            ull a0 = pk2(av.x, av.x), a1 = pk2(av.y, av.y), a2 = pk2(av.z, av.z), a3 = pk2(av.w, av.w);
#pragma unroll
            for (int j = 0; j < 4; j++) {
                ull bfrag = *(const ull*)&Bb[kk * 128 + tc * 2 + j * 32];
                acc[0][j] = fma2(a0, bfrag, acc[0][j]);
                acc[1][j] = fma2(a1, bfrag, acc[1][j]);
                acc[2][j] = fma2(a2, bfrag, acc[2][j]);
                acc[3][j] = fma2(a3, bfrag, acc[3][j]);
            }
        }
        if (s + 1 < U2_NS) {
            int ab = (buf ^ 1) * U2_BK * 68;
#pragma unroll
            for (int h = 0; h < 2; h++) {
                int kk = q * 8 + h * 4;
                As[ab + kk * 68 + ea] = ra[h].x; As[ab + (kk + 1) * 68 + ea] = ra[h].y;
                As[ab + (kk + 2) * 68 + ea] = ra[h].z; As[ab + (kk + 3) * 68 + ea] = ra[h].w;
            }
        }
        __syncthreads();
    }

#pragma unroll
    for (int r = 0; r < 4; r++) {
        int n = n0 + tr * 4 + r;
        if (n >= NN) continue;
#pragma unroll
        for (int j = 0; j < 4; j++) {
            int c = tc * 2 + j * 32;
            int cg = gy * 128 + c;
            float2 m = upk(acc[r][j]);
            m.x += b[cg]; m.y += b[cg + 1];
            if (gy < 2) {
                g_s[(size_t)n * SD + cg] += m.x;
                g_s[(size_t)n * SD + cg + 1] += m.y;
            } else {
                size_t vb = (size_t)n * 384;
#pragma unroll
                for (int cc = 0; cc < 3; cc++) {
                    g_v[vb + cc * 128 + c]     += g_vv[vb + cc * 128 + c] * m.x;
                    g_v[vb + cc * 128 + c + 1] += g_vv[vb + cc * 128 + c + 1] * m.y;
                }
            }
        }
    }
}

// ---------------- launch ----------------
extern "C" void kernel_launch(void* const* d_in, const int* in_sizes, int n_in,
                              void* d_out, int out_size) {
    const float* s_in   = (const float*)d_in[0];
    const float* v_in   = (const float*)d_in[1];
    const float* p_in   = (const float*)d_in[2];
    const int*   eidx   = (const int*)d_in[3];
    const float* edge_d = (const float*)d_in[4];
    const float* edge_a = (const float*)d_in[5];
    const float* rnorm  = (const float*)d_in[6];
    const float* edge_e = (const float*)d_in[7];
    const float* ohe    = (const float*)d_in[8];
    const float* eglob  = (const float*)d_in[9];
    const float* gamma  = (const float*)d_in[10];
    const float* beta   = (const float*)d_in[11];
    const float* We1    = (const float*)d_in[12];
    const float* be1    = (const float*)d_in[13];
    const float* We2    = (const float*)d_in[14];
    const float* be2    = (const float*)d_in[15];
    const float* Wvu    = (const float*)d_in[16];
    const float* Wu1    = (const float*)d_in[17];
    const float* bu1    = (const float*)d_in[18];
    const float* Wu2    = (const float*)d_in[19];
    const float* bu2    = (const float*)d_in[20];

    const int* src = eidx;
    const int* tgt = eidx + EE;
    float* out = (float*)d_out;

    cudaFuncSetAttribute(k_cmm,   cudaFuncAttributeMaxDynamicSharedMemorySize, CM_SMEM);
    cudaFuncSetAttribute(k_edge1, cudaFuncAttributeMaxDynamicSharedMemorySize, E1_SMEM);
    cudaFuncSetAttribute(k_gemm2, cudaFuncAttributeMaxDynamicSharedMemorySize, G2_SMEM);
    cudaFuncSetAttribute(k_u1,    cudaFuncAttributeMaxDynamicSharedMemorySize, U1_SMEM);
    cudaFuncSetAttribute(k_u2,    cudaFuncAttributeMaxDynamicSharedMemorySize, U2_SMEM);

    k_init<<<2048, 256>>>(s_in, v_in, p_in, edge_e, out);
    k_count<<<(EE + 255) / 256, 256>>>(tgt);
    k_icnt<<<(NN + 255) / 256, 256>>>();
    k_tail<<<(EE * TAILD + 255) / 256, 256>>>(edge_d, edge_a, edge_e, ohe, eglob);

    const int NBLK = (NN + 63) / 64;  // 157
    for (int i = 0; i < 5; i++) {
        const float* We1_i = We1 + (size_t)i * 600 * SD;
        k_prep<<<NN, 256>>>(gamma + i * 256, beta + i * 256);
        k_cmm<<<dim3(NBLK, 2), 256, CM_SMEM>>>(We1_i);
        k_edge1<<<EE / 64, 256, E1_SMEM>>>(src, tgt, We1_i + (size_t)512 * SD, be1 + i * 256);
        k_gemm2<<<dim3(EE / 64, 2), 256, G2_SMEM>>>(We2 + (size_t)i * SD * 512, be2 + i * 512, src, tgt, rnorm);
        k_add<<<NN, 384>>>();
        if (i < 4) {
            k_vv<<<NN, 128>>>(Wvu + (size_t)i * 128 * 128);
            k_u1<<<NBLK, 256, U1_SMEM>>>(Wu1 + (size_t)i * 384 * 256, bu1 + i * 256);
            k_u2<<<dim3(NBLK, 3), 256, U2_SMEM>>>(Wu2 + (size_t)i * 256 * 384, bu2 + i * 384);
        }
    }
    k_final<<<NN, 256>>>(gamma + 5 * 256, beta + 5 * 256, out, out + OFFV);
}